// round 11
// baseline (speedup 1.0000x reference)
#include <cuda_runtime.h>
#include <cuda_fp16.h>
#include <math.h>

#define N_ITEMS 7000
#define N_USERS 30000
#define N_NODES 37000
#define DIM     128
#define E_EDGES 400000
#define R_REL   10
#define NBASES  8
#define B_BATCH 512
#define L_CTX   100

#define SRC_BLKS 28              // ceil(7000/256)
#define DST_BLKS 118             // ceil(30000/256)

// ---------------- device scratch (static; no allocation) ----------------
__device__ __half g_wmsg[(size_t)R_REL * N_ITEMS * DIM];  // 17.9 MB (fp16)
__device__ __half g_userh[(size_t)N_USERS * DIM];         //  7.7 MB (fp16)
__device__ float  g_item[(size_t)N_ITEMS * DIM];          //  3.58 MB
__device__ float  g_score[N_ITEMS];
__device__ int    g_has[N_ITEMS];

__device__ int g_cnt_src[N_ITEMS];
__device__ int g_off_src[N_ITEMS];
__device__ int g_csr_src[E_EDGES];        // user-local id per edge, grouped by src item

__device__ int g_cnt_dst[N_USERS];
__device__ int g_off_dst[N_USERS];
__device__ int g_csr_dst[E_EDGES];        // packed src*16+type, grouped by dst user

__device__ __align__(16) unsigned int g_pack[E_EDGES];  // (s<<19)|(t<<15)|u
__device__ __align__(16) unsigned int g_rank[E_EDGES];  // (rank_src<<16)|rank_dst

__device__ int g_cursor[2];               // segment allocators (src, dst)

__device__ float g_pool[2 * B_BATCH * DIM];
__device__ int   g_is64;

__device__ __forceinline__ int geti(const void* p, long long i, int is64) {
    if (is64) return (int)((const long long*)p)[i];
    return ((const int*)p)[i];
}

// ---------------- wmsg table build + fused per-call state zeroing ----------------
__global__ void k_wmsg(const float* __restrict__ basis, const float* __restrict__ comp,
                       const int* __restrict__ ei32) {
    __shared__ float sc[R_REL * NBASES];
    int i = blockIdx.x;
    int d = threadIdx.x;
    // fused zeroing / dtype sniff (grid covers 7000*128 = 896k threads)
    int gid = i * DIM + d;
    if (gid == 0) {
        int s = 0;
        for (int k = 1; k < 64; k += 2) s |= ei32[k];  // int64 -> high words all 0
        g_is64 = (s == 0) ? 1 : 0;
        g_cursor[0] = 0;
        g_cursor[1] = 0;
    }
    if (gid < N_ITEMS) g_cnt_src[gid] = 0;
    if (gid < N_USERS) g_cnt_dst[gid] = 0;

    if (d < R_REL * NBASES) sc[d] = comp[d];
    __syncthreads();
    float bv[NBASES];
#pragma unroll
    for (int b = 0; b < NBASES; b++)
        bv[b] = basis[(size_t)b * N_NODES * DIM + (size_t)i * DIM + d];
#pragma unroll
    for (int r = 0; r < R_REL; r++) {
        float acc = 0.f;
#pragma unroll
        for (int b = 0; b < NBASES; b++) acc += sc[r * NBASES + b] * bv[b];
        g_wmsg[((size_t)r * N_ITEMS + i) * DIM + d] = __float2half(acc);
    }
}

// ---------------- histogram + edge packing + per-edge rank (2 edges/thread) ----------------
__global__ void k_hist(const void* __restrict__ ei, const void* __restrict__ et) {
    int i0 = (blockIdx.x * blockDim.x + threadIdx.x) * 2;
    if (i0 >= E_EDGES) return;
    int is64 = g_is64;
    int s[2], u[2], t[2];
#pragma unroll
    for (int q = 0; q < 2; q++) {
        int e = i0 + q;
        s[q] = geti(ei, e, is64);
        u[q] = geti(ei, (long long)E_EDGES + e, is64) - N_ITEMS;
        t[q] = geti(et, e, is64);
    }
#pragma unroll
    for (int q = 0; q < 2; q++)
        g_pack[i0 + q] = ((unsigned)s[q] << 19) | ((unsigned)t[q] << 15) | (unsigned)u[q];
    unsigned rs[2], rd[2];
#pragma unroll
    for (int q = 0; q < 2; q++) rs[q] = (unsigned)atomicAdd(&g_cnt_src[s[q]], 1);
#pragma unroll
    for (int q = 0; q < 2; q++) rd[q] = (unsigned)atomicAdd(&g_cnt_dst[u[q]], 1);
#pragma unroll
    for (int q = 0; q < 2; q++) g_rank[i0 + q] = (rs[q] << 16) | rd[q];
}

// ---------------- segment offsets: block scan + one atomic base per block ----------------
__global__ void k_off() {
    __shared__ int wsum[8];
    __shared__ int sbase;
    int b = blockIdx.x;
    const int* cnt;
    int* off;
    int* cursor;
    int n, i0;
    if (b < SRC_BLKS) { cnt = g_cnt_src; off = g_off_src; cursor = &g_cursor[0]; n = N_ITEMS; i0 = b * 256; }
    else              { cnt = g_cnt_dst; off = g_off_dst; cursor = &g_cursor[1]; n = N_USERS; i0 = (b - SRC_BLKS) * 256; }
    int lane = threadIdx.x & 31, w = threadIdx.x >> 5;
    int i = i0 + (int)threadIdx.x;
    int c = (i < n) ? cnt[i] : 0;
    int x = c;
#pragma unroll
    for (int o = 1; o < 32; o <<= 1) {
        int y = __shfl_up_sync(0xffffffffu, x, o);
        if (lane >= o) x += y;
    }
    if (lane == 31) wsum[w] = x;
    __syncthreads();
    if (threadIdx.x == 0) {
        int run = 0;
#pragma unroll
        for (int k = 0; k < 8; k++) { int t = wsum[k]; wsum[k] = run; run += t; }
        sbase = atomicAdd(cursor, run);
    }
    __syncthreads();
    if (i < n) off[i] = sbase + wsum[w] + x - c;
}

// ---------------- CSR scatter (atomic-free; 2 edges/thread) ----------------
__global__ void k_scatter() {
    int i0 = (blockIdx.x * blockDim.x + threadIdx.x) * 2;
    if (i0 >= E_EDGES) return;
    uint2 pk2 = *(const uint2*)&g_pack[i0];
    uint2 rk2 = *(const uint2*)&g_rank[i0];
    unsigned pk[2] = {pk2.x, pk2.y};
    unsigned rk[2] = {rk2.x, rk2.y};
    int po[2], qo[2];
#pragma unroll
    for (int q = 0; q < 2; q++) {
        po[q] = g_off_src[pk[q] >> 19];
        qo[q] = g_off_dst[pk[q] & 0x7fffu];
    }
#pragma unroll
    for (int q = 0; q < 2; q++) {
        int s = (int)(pk[q] >> 19);
        int t = (int)((pk[q] >> 15) & 15u);
        int u = (int)(pk[q] & 0x7fffu);
        g_csr_src[po[q] + (int)(rk[q] >> 16)] = u;
        g_csr_dst[qo[q] + (int)(rk[q] & 0xffffu)] = s * 16 + t;
    }
}

// ---------------- per-user embedding: root + bias + sum_r mean_r (fp16 gather, ILP4) ----------------
__global__ void k_user(const float* __restrict__ root, const float* __restrict__ bias) {
    __shared__ int   scnt[8][16];
    __shared__ float sinv[8][16];
    int w = threadIdx.x >> 5, lane = threadIdx.x & 31;
    int u = blockIdx.x * 8 + w;
    if (u >= N_USERS) return;
    int beg = g_off_dst[u];
    int end = beg + g_cnt_dst[u];
    if (lane < 16) scnt[w][lane] = 0;
    __syncwarp();
    for (int e = beg + lane; e < end; e += 32)
        atomicAdd(&scnt[w][g_csr_dst[e] & 15], 1);
    __syncwarp();
    if (lane < 16)
        sinv[w][lane] = scnt[w][lane] > 0 ? 1.f / (float)scnt[w][lane] : 0.f;
    __syncwarp();
    float4 acc = make_float4(0.f, 0.f, 0.f, 0.f);
    for (int e = beg; e < end; e += 4) {
        int   pk[4];
        float mk[4];
        uint2 v[4];
#pragma unroll
        for (int q = 0; q < 4; q++) {
            int ee = e + q;
            bool ok = ee < end;
            pk[q] = g_csr_dst[ok ? ee : beg];
            mk[q] = ok ? 1.f : 0.f;
        }
#pragma unroll
        for (int q = 0; q < 4; q++)
            v[q] = ((const uint2*)(g_wmsg + ((size_t)(pk[q] & 15) * N_ITEMS + (pk[q] >> 4)) * DIM))[lane];
#pragma unroll
        for (int q = 0; q < 4; q++) {
            float iv = mk[q] * sinv[w][pk[q] & 15];
            float2 f0 = __half22float2(*(const __half2*)&v[q].x);
            float2 f1 = __half22float2(*(const __half2*)&v[q].y);
            acc.x += iv * f0.x; acc.y += iv * f0.y;
            acc.z += iv * f1.x; acc.w += iv * f1.y;
        }
    }
    int g = N_ITEMS + u;
    float4 rv = ((const float4*)&root[(size_t)g * DIM])[lane];
    float4 bv = ((const float4*)bias)[lane];
    uint2 o;
    *(__half2*)&o.x = __floats2half2_rn(acc.x + rv.x + bv.x, acc.y + rv.y + bv.y);
    *(__half2*)&o.y = __floats2half2_rn(acc.z + rv.z + bv.z, acc.w + rv.w + bv.w);
    ((uint2*)(g_userh + (size_t)u * DIM))[lane] = o;
}

// ---------------- per-item mean of connected users (fp16 gather, ILP4) ----------------
__global__ void k_item() {
    int w = threadIdx.x >> 5, lane = threadIdx.x & 31;
    int i = blockIdx.x * 8 + w;
    if (i >= N_ITEMS) return;
    int beg = g_off_src[i];
    int deg = g_cnt_src[i];
    int end = beg + deg;
    float4 acc = make_float4(0.f, 0.f, 0.f, 0.f);
    for (int e = beg; e < end; e += 4) {
        float mk[4];
        uint2 v[4];
        int   uu[4];
#pragma unroll
        for (int q = 0; q < 4; q++) {
            int ee = e + q;
            bool ok = ee < end;
            uu[q] = g_csr_src[ok ? ee : beg];
            mk[q] = ok ? 1.f : 0.f;
        }
#pragma unroll
        for (int q = 0; q < 4; q++)
            v[q] = ((const uint2*)(g_userh + (size_t)uu[q] * DIM))[lane];
#pragma unroll
        for (int q = 0; q < 4; q++) {
            float2 f0 = __half22float2(*(const __half2*)&v[q].x);
            float2 f1 = __half22float2(*(const __half2*)&v[q].y);
            acc.x += mk[q] * f0.x; acc.y += mk[q] * f0.y;
            acc.z += mk[q] * f1.x; acc.w += mk[q] * f1.y;
        }
    }
    float iv = deg > 0 ? 1.f / (float)deg : 0.f;
    ((float4*)&g_item[((size_t)i * DIM)])[lane] =
        make_float4(acc.x * iv, acc.y * iv, acc.z * iv, acc.w * iv);
    if (lane == 0) g_has[i] = (deg > 0) ? 1 : 0;
}

// ---------------- batched per-item attention score: tanh(h@A)·b ----------------
#define IPB 32
__global__ void k_score(const float* __restrict__ attn_a, const float* __restrict__ attn_b) {
    __shared__ float h[IPB][DIM];
    __shared__ float sc[IPB][DIM + 1];
    int i0 = blockIdx.x * IPB;
    int tid = threadIdx.x;      // 128
    for (int idx = tid; idx < IPB * DIM / 4; idx += 128) {
        int ii = idx / (DIM / 4), kk = idx % (DIM / 4);
        float4 v = (i0 + ii < N_ITEMS)
                   ? ((const float4*)&g_item[(size_t)(i0 + ii) * DIM])[kk]
                   : make_float4(0.f, 0.f, 0.f, 0.f);
        ((float4*)h[ii])[kk] = v;
    }
    __syncthreads();
    int j = tid;
    float acc[IPB];
#pragma unroll
    for (int i = 0; i < IPB; i++) acc[i] = 0.f;
#pragma unroll 4
    for (int k = 0; k < DIM; k++) {
        float a = attn_a[k * DIM + j];
#pragma unroll
        for (int i = 0; i < IPB; i++) acc[i] += h[i][k] * a;
    }
    float bj = attn_b[j];
#pragma unroll
    for (int i = 0; i < IPB; i++) sc[i][j] = tanhf(acc[i]) * bj;
    __syncthreads();
    if (tid < IPB) {
        float s = 0.f;
        for (int jj = 0; jj < DIM; jj++) s += sc[tid][jj];
        if (i0 + tid < N_ITEMS) g_score[i0 + tid] = s;
    }
}

// ---------------- masked softmax pooling (both contexts fused) ----------------
__global__ void k_pool(const void* __restrict__ ctx_i, const void* __restrict__ ctx_r) {
    __shared__ float sw[DIM];
    __shared__ int   sidx[DIM];
    int b = blockIdx.x, tid = threadIdx.x;
    const void* ctx = (b < B_BATCH) ? ctx_i : ctx_r;
    int bs = (b < B_BATCH) ? b : b - B_BATCH;
    int is64 = g_is64;
    float val = -1e30f; int idx = -1;
    if (tid < L_CTX) {
        int c = geti(ctx, (long long)bs * L_CTX + tid, is64);
        if (c >= 0 && g_has[c]) { idx = c; val = g_score[c]; }
    }
    sw[tid] = val; sidx[tid] = idx;
    __syncthreads();
    for (int o = 64; o > 0; o >>= 1) {
        if (tid < o) sw[tid] = fmaxf(sw[tid], sw[tid + o]);
        __syncthreads();
    }
    float m = sw[0];
    __syncthreads();
    float ex = (idx >= 0) ? expf(val - m) : 0.f;
    sw[tid] = ex;
    __syncthreads();
    for (int o = 64; o > 0; o >>= 1) {
        if (tid < o) sw[tid] += sw[tid + o];
        __syncthreads();
    }
    float s = sw[0];
    float invs = (s > 0.f) ? 1.f / s : 0.f;
    __syncthreads();
    sw[tid] = ex;
    __syncthreads();
    float acc = 0.f;
#pragma unroll 4
    for (int l = 0; l < L_CTX; l++) {
        float wgt = sw[l];
        if (wgt > 0.f) acc += wgt * g_item[(size_t)sidx[l] * DIM + tid];
    }
    g_pool[(size_t)b * DIM + tid] = acc * invs;
}

// ---------------- fused MLP: proj (both contexts) + eproj, paired rows ----------------
// Block b handles init rows r0..r0+7 (pool rows r0..) and resp rows (pool rows 512+r0..).
#define PRB 8
__global__ void k_mlp(const float* __restrict__ W1, const float* __restrict__ b1,
                      const float* __restrict__ W2, const float* __restrict__ b2,
                      const float* __restrict__ eW1, const float* __restrict__ eb1,
                      const float* __restrict__ eW2, const float* __restrict__ eb2,
                      float* __restrict__ out) {
    __shared__ float xs[2 * PRB][DIM];   // inputs / hidden (reused)
    __shared__ float ys[2 * PRB][DIM];   // projection outputs
    int j = threadIdx.x & 127, h = threadIdx.x >> 7;   // 256 threads
    int r0 = blockIdx.x * PRB;
    float* p_init = out + B_BATCH * DIM;
    float* p_resp = out + 2 * B_BATCH * DIM;

    // load pooled rows: local 0..7 = init, 8..15 = resp
    for (int idx = threadIdx.x; idx < PRB * DIM / 4; idx += 256) {
        int rr = idx / (DIM / 4), kk = idx % (DIM / 4);
        ((float4*)&xs[rr][0])[kk]       = ((const float4*)g_pool)[(size_t)(r0 + rr) * (DIM / 4) + kk];
        ((float4*)&xs[PRB + rr][0])[kk] = ((const float4*)g_pool)[(size_t)(B_BATCH + r0 + rr) * (DIM / 4) + kk];
    }
    __syncthreads();

    int rb = h * PRB;   // each half handles 8 of the 16 local rows
    float acc[PRB];
    // layer 1
    float bb = b1[j];
#pragma unroll
    for (int r = 0; r < PRB; r++) acc[r] = bb;
#pragma unroll 4
    for (int k = 0; k < DIM; k++) {
        float wv = W1[k * DIM + j];
#pragma unroll
        for (int r = 0; r < PRB; r++) acc[r] += xs[rb + r][k] * wv;
    }
    __syncthreads();
#pragma unroll
    for (int r = 0; r < PRB; r++) xs[rb + r][j] = fmaxf(acc[r], 0.f);
    __syncthreads();
    // layer 2 -> ys and global p_init/p_resp
    float bb2 = b2[j];
#pragma unroll
    for (int r = 0; r < PRB; r++) acc[r] = bb2;
#pragma unroll 4
    for (int k = 0; k < DIM; k++) {
        float wv = W2[k * DIM + j];
#pragma unroll
        for (int r = 0; r < PRB; r++) acc[r] += xs[rb + r][k] * wv;
    }
#pragma unroll
    for (int r = 0; r < PRB; r++) {
        int lr = rb + r;
        float val = fmaxf(acc[r], 0.f);
        ys[lr][j] = val;
        if (lr < PRB) p_init[(size_t)(r0 + lr) * DIM + j] = val;
        else          p_resp[(size_t)(r0 + lr - PRB) * DIM + j] = val;
    }
    __syncthreads();

    // eproj on the 8 pairs: x2 = [ys[r], ys[PRB+r]] (256-dim)
    int erb = h * (PRB / 2);   // each half handles 4 pairs
    float eacc[PRB / 2];
    float ebb = eb1[j];
#pragma unroll
    for (int r = 0; r < PRB / 2; r++) eacc[r] = ebb;
#pragma unroll 4
    for (int k = 0; k < DIM; k++) {
        float wv0 = eW1[k * DIM + j];
        float wv1 = eW1[(DIM + k) * DIM + j];
#pragma unroll
        for (int r = 0; r < PRB / 2; r++)
            eacc[r] += ys[erb + r][k] * wv0 + ys[PRB + erb + r][k] * wv1;
    }
    __syncthreads();
#pragma unroll
    for (int r = 0; r < PRB / 2; r++) xs[erb + r][j] = fmaxf(eacc[r], 0.f);
    __syncthreads();
    float ebb2 = eb2[j];
#pragma unroll
    for (int r = 0; r < PRB / 2; r++) eacc[r] = ebb2;
#pragma unroll 4
    for (int k = 0; k < DIM; k++) {
        float wv = eW2[k * DIM + j];
#pragma unroll
        for (int r = 0; r < PRB / 2; r++) eacc[r] += xs[erb + r][k] * wv;
    }
#pragma unroll
    for (int r = 0; r < PRB / 2; r++)
        out[(size_t)(r0 + erb + r) * DIM + j] = fmaxf(eacc[r], 0.f);
}

// ---------------- launch ----------------
extern "C" void kernel_launch(void* const* d_in, const int* in_sizes, int n_in,
                              void* d_out, int out_size) {
    const void*  ei     = d_in[0];
    const void*  et     = d_in[1];
    const void*  ctx_i  = d_in[2];
    const void*  ctx_r  = d_in[3];
    const float* basis  = (const float*)d_in[4];
    const float* comp   = (const float*)d_in[5];
    const float* root   = (const float*)d_in[6];
    const float* bias   = (const float*)d_in[7];
    const float* attn_a = (const float*)d_in[8];
    const float* attn_b = (const float*)d_in[9];
    const float* fc1_w  = (const float*)d_in[10];
    const float* fc1_b  = (const float*)d_in[11];
    const float* fc2_w  = (const float*)d_in[12];
    const float* fc2_b  = (const float*)d_in[13];
    const float* efc1_w = (const float*)d_in[14];
    const float* efc1_b = (const float*)d_in[15];
    const float* efc2_w = (const float*)d_in[16];
    const float* efc2_b = (const float*)d_in[17];
    float* out = (float*)d_out;

    k_wmsg<<<N_ITEMS, DIM>>>(basis, comp, (const int*)ei);
    k_hist<<<(E_EDGES / 2 + 255) / 256, 256>>>(ei, et);
    k_off<<<SRC_BLKS + DST_BLKS, 256>>>();
    k_scatter<<<(E_EDGES / 2 + 255) / 256, 256>>>();
    k_user<<<N_USERS / 8, 256>>>(root, bias);
    k_item<<<N_ITEMS / 8, 256>>>();
    k_score<<<(N_ITEMS + IPB - 1) / IPB, 128>>>(attn_a, attn_b);
    k_pool<<<2 * B_BATCH, DIM>>>(ctx_i, ctx_r);
    k_mlp<<<B_BATCH / PRB, 256>>>(fc1_w, fc1_b, fc2_w, fc2_b,
                                  efc1_w, efc1_b, efc2_w, efc2_b, out);
}

// round 12
// speedup vs baseline: 1.1166x; 1.1166x over previous
#include <cuda_runtime.h>
#include <cuda_fp16.h>
#include <math.h>

#define N_ITEMS 7000
#define N_USERS 30000
#define N_NODES 37000
#define DIM     128
#define E_EDGES 400000
#define R_REL   10
#define NBASES  8
#define B_BATCH 512
#define L_CTX   100

#define SRC_BLKS 28              // ceil(7000/256)
#define DST_BLKS 118             // ceil(30000/256)

// ---------------- device scratch (static; no allocation) ----------------
__device__ __half g_wmsg[(size_t)R_REL * N_ITEMS * DIM];  // 17.9 MB (fp16)
__device__ __half g_userh[(size_t)N_USERS * DIM];         //  7.7 MB (fp16)
__device__ float  g_item[(size_t)N_ITEMS * DIM];          //  3.58 MB
__device__ float  g_score[N_ITEMS];
__device__ int    g_has[N_ITEMS];

__device__ int g_cnt_src[N_ITEMS];
__device__ int g_off_src[N_ITEMS];
__device__ int g_csr_src[E_EDGES];        // user-local id per edge, grouped by src item

__device__ int g_cnt_dst[N_USERS];
__device__ int g_off_dst[N_USERS];
__device__ int g_csr_dst[E_EDGES];        // packed src*16+type, grouped by dst user

__device__ __align__(16) unsigned int g_pack[E_EDGES];  // (s<<19)|(t<<15)|u
__device__ __align__(16) unsigned int g_rank[E_EDGES];  // (rank_src<<16)|rank_dst

__device__ int g_cursor[2];               // segment allocators (src, dst)

__device__ float g_pool[2 * B_BATCH * DIM];
__device__ int   g_is64;

__device__ __forceinline__ int geti(const void* p, long long i, int is64) {
    if (is64) return (int)((const long long*)p)[i];
    return ((const int*)p)[i];
}

// ---------------- wmsg table build + fused per-call state zeroing ----------------
__global__ void k_wmsg(const float* __restrict__ basis, const float* __restrict__ comp,
                       const int* __restrict__ ei32) {
    __shared__ float sc[R_REL * NBASES];
    int i = blockIdx.x;
    int d = threadIdx.x;
    int gid = i * DIM + d;
    if (gid == 0) {
        int s = 0;
        for (int k = 1; k < 64; k += 2) s |= ei32[k];  // int64 -> high words all 0
        g_is64 = (s == 0) ? 1 : 0;
        g_cursor[0] = 0;
        g_cursor[1] = 0;
    }
    if (gid < N_ITEMS) g_cnt_src[gid] = 0;
    if (gid < N_USERS) g_cnt_dst[gid] = 0;

    if (d < R_REL * NBASES) sc[d] = comp[d];
    __syncthreads();
    float bv[NBASES];
#pragma unroll
    for (int b = 0; b < NBASES; b++)
        bv[b] = basis[(size_t)b * N_NODES * DIM + (size_t)i * DIM + d];
#pragma unroll
    for (int r = 0; r < R_REL; r++) {
        float acc = 0.f;
#pragma unroll
        for (int b = 0; b < NBASES; b++) acc += sc[r * NBASES + b] * bv[b];
        g_wmsg[((size_t)r * N_ITEMS + i) * DIM + d] = __float2half(acc);
    }
}

// ---------------- histogram + edge packing + per-edge rank (2 edges/thread) ----------------
__global__ void k_hist(const void* __restrict__ ei, const void* __restrict__ et) {
    int i0 = (blockIdx.x * blockDim.x + threadIdx.x) * 2;
    if (i0 >= E_EDGES) return;
    int is64 = g_is64;
    int s[2], u[2], t[2];
#pragma unroll
    for (int q = 0; q < 2; q++) {
        int e = i0 + q;
        s[q] = geti(ei, e, is64);
        u[q] = geti(ei, (long long)E_EDGES + e, is64) - N_ITEMS;
        t[q] = geti(et, e, is64);
    }
#pragma unroll
    for (int q = 0; q < 2; q++)
        g_pack[i0 + q] = ((unsigned)s[q] << 19) | ((unsigned)t[q] << 15) | (unsigned)u[q];
    unsigned rs[2], rd[2];
#pragma unroll
    for (int q = 0; q < 2; q++) rs[q] = (unsigned)atomicAdd(&g_cnt_src[s[q]], 1);
#pragma unroll
    for (int q = 0; q < 2; q++) rd[q] = (unsigned)atomicAdd(&g_cnt_dst[u[q]], 1);
#pragma unroll
    for (int q = 0; q < 2; q++) g_rank[i0 + q] = (rs[q] << 16) | rd[q];
}

// ---------------- segment offsets: block scan + one atomic base per block ----------------
__global__ void k_off() {
    __shared__ int wsum[8];
    __shared__ int sbase;
    int b = blockIdx.x;
    const int* cnt;
    int* off;
    int* cursor;
    int n, i0;
    if (b < SRC_BLKS) { cnt = g_cnt_src; off = g_off_src; cursor = &g_cursor[0]; n = N_ITEMS; i0 = b * 256; }
    else              { cnt = g_cnt_dst; off = g_off_dst; cursor = &g_cursor[1]; n = N_USERS; i0 = (b - SRC_BLKS) * 256; }
    int lane = threadIdx.x & 31, w = threadIdx.x >> 5;
    int i = i0 + (int)threadIdx.x;
    int c = (i < n) ? cnt[i] : 0;
    int x = c;
#pragma unroll
    for (int o = 1; o < 32; o <<= 1) {
        int y = __shfl_up_sync(0xffffffffu, x, o);
        if (lane >= o) x += y;
    }
    if (lane == 31) wsum[w] = x;
    __syncthreads();
    if (threadIdx.x == 0) {
        int run = 0;
#pragma unroll
        for (int k = 0; k < 8; k++) { int t = wsum[k]; wsum[k] = run; run += t; }
        sbase = atomicAdd(cursor, run);
    }
    __syncthreads();
    if (i < n) off[i] = sbase + wsum[w] + x - c;
}

// ---------------- CSR scatter (atomic-free; 2 edges/thread) ----------------
__global__ void k_scatter() {
    int i0 = (blockIdx.x * blockDim.x + threadIdx.x) * 2;
    if (i0 >= E_EDGES) return;
    uint2 pk2 = *(const uint2*)&g_pack[i0];
    uint2 rk2 = *(const uint2*)&g_rank[i0];
    unsigned pk[2] = {pk2.x, pk2.y};
    unsigned rk[2] = {rk2.x, rk2.y};
    int po[2], qo[2];
#pragma unroll
    for (int q = 0; q < 2; q++) {
        po[q] = g_off_src[pk[q] >> 19];
        qo[q] = g_off_dst[pk[q] & 0x7fffu];
    }
#pragma unroll
    for (int q = 0; q < 2; q++) {
        int s = (int)(pk[q] >> 19);
        int t = (int)((pk[q] >> 15) & 15u);
        int u = (int)(pk[q] & 0x7fffu);
        g_csr_src[po[q] + (int)(rk[q] >> 16)] = u;
        g_csr_dst[qo[q] + (int)(rk[q] & 0xffffu)] = s * 16 + t;
    }
}

// ---------------- per-user embedding (LDG.128 gather: 2 edges/slot, 4 slots) ----------------
__global__ void k_user(const float* __restrict__ root, const float* __restrict__ bias) {
    __shared__ int   scnt[8][16];
    __shared__ float sinv[8][16];
    int w = threadIdx.x >> 5, lane = threadIdx.x & 31;
    int u = blockIdx.x * 8 + w;
    if (u >= N_USERS) return;
    int beg = g_off_dst[u];
    int end = beg + g_cnt_dst[u];
    if (lane < 16) scnt[w][lane] = 0;
    __syncwarp();
    for (int e = beg + lane; e < end; e += 32)
        atomicAdd(&scnt[w][g_csr_dst[e] & 15], 1);
    __syncwarp();
    if (lane < 16)
        sinv[w][lane] = scnt[w][lane] > 0 ? 1.f / (float)scnt[w][lane] : 0.f;
    __syncwarp();

    int half = lane >> 4;     // 0: even edge of pair, 1: odd edge
    int hl   = lane & 15;     // 16 lanes cover one 256B fp16 row
    float acc[8];
#pragma unroll
    for (int i = 0; i < 8; i++) acc[i] = 0.f;

    for (int e = beg; e < end; e += 8) {
        int   pk[4];
        float mk[4];
        uint4 v[4];
#pragma unroll
        for (int q = 0; q < 4; q++) {
            int ee = e + 2 * q + half;
            bool ok = ee < end;
            pk[q] = g_csr_dst[ok ? ee : beg];
            mk[q] = ok ? 1.f : 0.f;
        }
#pragma unroll
        for (int q = 0; q < 4; q++)
            v[q] = ((const uint4*)(g_wmsg + ((size_t)(pk[q] & 15) * N_ITEMS + (pk[q] >> 4)) * DIM))[hl];
#pragma unroll
        for (int q = 0; q < 4; q++) {
            float iv = mk[q] * sinv[w][pk[q] & 15];
            float2 f0 = __half22float2(*(const __half2*)&v[q].x);
            float2 f1 = __half22float2(*(const __half2*)&v[q].y);
            float2 f2 = __half22float2(*(const __half2*)&v[q].z);
            float2 f3 = __half22float2(*(const __half2*)&v[q].w);
            acc[0] += iv * f0.x; acc[1] += iv * f0.y;
            acc[2] += iv * f1.x; acc[3] += iv * f1.y;
            acc[4] += iv * f2.x; acc[5] += iv * f2.y;
            acc[6] += iv * f3.x; acc[7] += iv * f3.y;
        }
    }
    // merge even/odd halves: lane l pairs with l^16
#pragma unroll
    for (int i = 0; i < 8; i++)
        acc[i] += __shfl_xor_sync(0xffffffffu, acc[i], 16);

    if (half == 0) {
        const float4* rp = (const float4*)(root + (size_t)(N_ITEMS + u) * DIM + 8 * hl);
        const float4* bp = (const float4*)(bias + 8 * hl);
        float4 r0 = rp[0], r1 = rp[1];
        float4 b0 = bp[0], b1 = bp[1];
        uint4 o;
        *(__half2*)&o.x = __floats2half2_rn(acc[0] + r0.x + b0.x, acc[1] + r0.y + b0.y);
        *(__half2*)&o.y = __floats2half2_rn(acc[2] + r0.z + b0.z, acc[3] + r0.w + b0.w);
        *(__half2*)&o.z = __floats2half2_rn(acc[4] + r1.x + b1.x, acc[5] + r1.y + b1.y);
        *(__half2*)&o.w = __floats2half2_rn(acc[6] + r1.z + b1.z, acc[7] + r1.w + b1.w);
        ((uint4*)(g_userh + (size_t)u * DIM))[hl] = o;
    }
}

// ---------------- per-item mean of users (LDG.128 gather: 2 edges/slot, 4 slots) ----------------
__global__ void k_item() {
    int w = threadIdx.x >> 5, lane = threadIdx.x & 31;
    int i = blockIdx.x * 8 + w;
    if (i >= N_ITEMS) return;
    int beg = g_off_src[i];
    int deg = g_cnt_src[i];
    int end = beg + deg;
    int half = lane >> 4;
    int hl   = lane & 15;
    float acc[8];
#pragma unroll
    for (int q = 0; q < 8; q++) acc[q] = 0.f;

    for (int e = beg; e < end; e += 8) {
        float mk[4];
        uint4 v[4];
        int   uu[4];
#pragma unroll
        for (int q = 0; q < 4; q++) {
            int ee = e + 2 * q + half;
            bool ok = ee < end;
            uu[q] = g_csr_src[ok ? ee : beg];
            mk[q] = ok ? 1.f : 0.f;
        }
#pragma unroll
        for (int q = 0; q < 4; q++)
            v[q] = ((const uint4*)(g_userh + (size_t)uu[q] * DIM))[hl];
#pragma unroll
        for (int q = 0; q < 4; q++) {
            float2 f0 = __half22float2(*(const __half2*)&v[q].x);
            float2 f1 = __half22float2(*(const __half2*)&v[q].y);
            float2 f2 = __half22float2(*(const __half2*)&v[q].z);
            float2 f3 = __half22float2(*(const __half2*)&v[q].w);
            acc[0] += mk[q] * f0.x; acc[1] += mk[q] * f0.y;
            acc[2] += mk[q] * f1.x; acc[3] += mk[q] * f1.y;
            acc[4] += mk[q] * f2.x; acc[5] += mk[q] * f2.y;
            acc[6] += mk[q] * f3.x; acc[7] += mk[q] * f3.y;
        }
    }
#pragma unroll
    for (int q = 0; q < 8; q++)
        acc[q] += __shfl_xor_sync(0xffffffffu, acc[q], 16);

    float iv = deg > 0 ? 1.f / (float)deg : 0.f;
    if (half == 0) {
        float* op = g_item + (size_t)i * DIM + 8 * hl;
        ((float4*)op)[0] = make_float4(acc[0] * iv, acc[1] * iv, acc[2] * iv, acc[3] * iv);
        ((float4*)op)[1] = make_float4(acc[4] * iv, acc[5] * iv, acc[6] * iv, acc[7] * iv);
    }
    if (lane == 0) g_has[i] = (deg > 0) ? 1 : 0;
}

// ---------------- batched per-item attention score: tanh(h@A)·b ----------------
#define IPB 32
__global__ void k_score(const float* __restrict__ attn_a, const float* __restrict__ attn_b) {
    __shared__ float h[IPB][DIM];
    __shared__ float sc[IPB][DIM + 1];
    int i0 = blockIdx.x * IPB;
    int tid = threadIdx.x;      // 128
    for (int idx = tid; idx < IPB * DIM / 4; idx += 128) {
        int ii = idx / (DIM / 4), kk = idx % (DIM / 4);
        float4 v = (i0 + ii < N_ITEMS)
                   ? ((const float4*)&g_item[(size_t)(i0 + ii) * DIM])[kk]
                   : make_float4(0.f, 0.f, 0.f, 0.f);
        ((float4*)h[ii])[kk] = v;
    }
    __syncthreads();
    int j = tid;
    float acc[IPB];
#pragma unroll
    for (int i = 0; i < IPB; i++) acc[i] = 0.f;
#pragma unroll 4
    for (int k = 0; k < DIM; k++) {
        float a = attn_a[k * DIM + j];
#pragma unroll
        for (int i = 0; i < IPB; i++) acc[i] += h[i][k] * a;
    }
    float bj = attn_b[j];
#pragma unroll
    for (int i = 0; i < IPB; i++) sc[i][j] = tanhf(acc[i]) * bj;
    __syncthreads();
    if (tid < IPB) {
        float s = 0.f;
        for (int jj = 0; jj < DIM; jj++) s += sc[tid][jj];
        if (i0 + tid < N_ITEMS) g_score[i0 + tid] = s;
    }
}

// ---------------- masked softmax pooling (both contexts fused) ----------------
__global__ void k_pool(const void* __restrict__ ctx_i, const void* __restrict__ ctx_r) {
    __shared__ float sw[DIM];
    __shared__ int   sidx[DIM];
    int b = blockIdx.x, tid = threadIdx.x;
    const void* ctx = (b < B_BATCH) ? ctx_i : ctx_r;
    int bs = (b < B_BATCH) ? b : b - B_BATCH;
    int is64 = g_is64;
    float val = -1e30f; int idx = -1;
    if (tid < L_CTX) {
        int c = geti(ctx, (long long)bs * L_CTX + tid, is64);
        if (c >= 0 && g_has[c]) { idx = c; val = g_score[c]; }
    }
    sw[tid] = val; sidx[tid] = idx;
    __syncthreads();
    for (int o = 64; o > 0; o >>= 1) {
        if (tid < o) sw[tid] = fmaxf(sw[tid], sw[tid + o]);
        __syncthreads();
    }
    float m = sw[0];
    __syncthreads();
    float ex = (idx >= 0) ? expf(val - m) : 0.f;
    sw[tid] = ex;
    __syncthreads();
    for (int o = 64; o > 0; o >>= 1) {
        if (tid < o) sw[tid] += sw[tid + o];
        __syncthreads();
    }
    float s = sw[0];
    float invs = (s > 0.f) ? 1.f / s : 0.f;
    __syncthreads();
    sw[tid] = ex;
    __syncthreads();
    float acc = 0.f;
#pragma unroll 4
    for (int l = 0; l < L_CTX; l++) {
        float wgt = sw[l];
        if (wgt > 0.f) acc += wgt * g_item[(size_t)sidx[l] * DIM + tid];
    }
    g_pool[(size_t)b * DIM + tid] = acc * invs;
}

// ---------------- fused MLP: proj (both contexts) + eproj, paired rows ----------------
#define PRB 8
__global__ void k_mlp(const float* __restrict__ W1, const float* __restrict__ b1,
                      const float* __restrict__ W2, const float* __restrict__ b2,
                      const float* __restrict__ eW1, const float* __restrict__ eb1,
                      const float* __restrict__ eW2, const float* __restrict__ eb2,
                      float* __restrict__ out) {
    __shared__ float xs[2 * PRB][DIM];
    __shared__ float ys[2 * PRB][DIM];
    int j = threadIdx.x & 127, h = threadIdx.x >> 7;   // 256 threads
    int r0 = blockIdx.x * PRB;
    float* p_init = out + B_BATCH * DIM;
    float* p_resp = out + 2 * B_BATCH * DIM;

    for (int idx = threadIdx.x; idx < PRB * DIM / 4; idx += 256) {
        int rr = idx / (DIM / 4), kk = idx % (DIM / 4);
        ((float4*)&xs[rr][0])[kk]       = ((const float4*)g_pool)[(size_t)(r0 + rr) * (DIM / 4) + kk];
        ((float4*)&xs[PRB + rr][0])[kk] = ((const float4*)g_pool)[(size_t)(B_BATCH + r0 + rr) * (DIM / 4) + kk];
    }
    __syncthreads();

    int rb = h * PRB;
    float acc[PRB];
    float bb = b1[j];
#pragma unroll
    for (int r = 0; r < PRB; r++) acc[r] = bb;
#pragma unroll 4
    for (int k = 0; k < DIM; k++) {
        float wv = W1[k * DIM + j];
#pragma unroll
        for (int r = 0; r < PRB; r++) acc[r] += xs[rb + r][k] * wv;
    }
    __syncthreads();
#pragma unroll
    for (int r = 0; r < PRB; r++) xs[rb + r][j] = fmaxf(acc[r], 0.f);
    __syncthreads();
    float bb2 = b2[j];
#pragma unroll
    for (int r = 0; r < PRB; r++) acc[r] = bb2;
#pragma unroll 4
    for (int k = 0; k < DIM; k++) {
        float wv = W2[k * DIM + j];
#pragma unroll
        for (int r = 0; r < PRB; r++) acc[r] += xs[rb + r][k] * wv;
    }
#pragma unroll
    for (int r = 0; r < PRB; r++) {
        int lr = rb + r;
        float val = fmaxf(acc[r], 0.f);
        ys[lr][j] = val;
        if (lr < PRB) p_init[(size_t)(r0 + lr) * DIM + j] = val;
        else          p_resp[(size_t)(r0 + lr - PRB) * DIM + j] = val;
    }
    __syncthreads();

    int erb = h * (PRB / 2);
    float eacc[PRB / 2];
    float ebb = eb1[j];
#pragma unroll
    for (int r = 0; r < PRB / 2; r++) eacc[r] = ebb;
#pragma unroll 4
    for (int k = 0; k < DIM; k++) {
        float wv0 = eW1[k * DIM + j];
        float wv1 = eW1[(DIM + k) * DIM + j];
#pragma unroll
        for (int r = 0; r < PRB / 2; r++)
            eacc[r] += ys[erb + r][k] * wv0 + ys[PRB + erb + r][k] * wv1;
    }
    __syncthreads();
#pragma unroll
    for (int r = 0; r < PRB / 2; r++) xs[erb + r][j] = fmaxf(eacc[r], 0.f);
    __syncthreads();
    float ebb2 = eb2[j];
#pragma unroll
    for (int r = 0; r < PRB / 2; r++) eacc[r] = ebb2;
#pragma unroll 4
    for (int k = 0; k < DIM; k++) {
        float wv = eW2[k * DIM + j];
#pragma unroll
        for (int r = 0; r < PRB / 2; r++) eacc[r] += xs[erb + r][k] * wv;
    }
#pragma unroll
    for (int r = 0; r < PRB / 2; r++)
        out[(size_t)(r0 + erb + r) * DIM + j] = fmaxf(eacc[r], 0.f);
}

// ---------------- launch ----------------
extern "C" void kernel_launch(void* const* d_in, const int* in_sizes, int n_in,
                              void* d_out, int out_size) {
    const void*  ei     = d_in[0];
    const void*  et     = d_in[1];
    const void*  ctx_i  = d_in[2];
    const void*  ctx_r  = d_in[3];
    const float* basis  = (const float*)d_in[4];
    const float* comp   = (const float*)d_in[5];
    const float* root   = (const float*)d_in[6];
    const float* bias   = (const float*)d_in[7];
    const float* attn_a = (const float*)d_in[8];
    const float* attn_b = (const float*)d_in[9];
    const float* fc1_w  = (const float*)d_in[10];
    const float* fc1_b  = (const float*)d_in[11];
    const float* fc2_w  = (const float*)d_in[12];
    const float* fc2_b  = (const float*)d_in[13];
    const float* efc1_w = (const float*)d_in[14];
    const float* efc1_b = (const float*)d_in[15];
    const float* efc2_w = (const float*)d_in[16];
    const float* efc2_b = (const float*)d_in[17];
    float* out = (float*)d_out;

    k_wmsg<<<N_ITEMS, DIM>>>(basis, comp, (const int*)ei);
    k_hist<<<(E_EDGES / 2 + 255) / 256, 256>>>(ei, et);
    k_off<<<SRC_BLKS + DST_BLKS, 256>>>();
    k_scatter<<<(E_EDGES / 2 + 255) / 256, 256>>>();
    k_user<<<N_USERS / 8, 256>>>(root, bias);
    k_item<<<N_ITEMS / 8, 256>>>();
    k_score<<<(N_ITEMS + IPB - 1) / IPB, 128>>>(attn_a, attn_b);
    k_pool<<<2 * B_BATCH, DIM>>>(ctx_i, ctx_r);
    k_mlp<<<B_BATCH / PRB, 256>>>(fc1_w, fc1_b, fc2_w, fc2_b,
                                  efc1_w, efc1_b, efc2_w, efc2_b, out);
}